// round 15
// baseline (speedup 1.0000x reference)
#include <cuda_runtime.h>
#include <math.h>

#define DIM 4096
#define HID 8192
#define ALPHA 0.1f
#define LOG_ALPHA -2.3025850929940457f

#define GRID  512
#define NTHR  512
#define NSLAB 128              // partial slabs
#define BROWS (HID / NSLAB)    // 64 rows per slab
#define XCH   4                // column chunks in phase 1
#define CCH   (DIM / XCH)      // 1024 cols per chunk

// Scratch (device globals). Partials: 4 x 2MB = 8MB.
static __device__ __align__(16) float g_pAv[(size_t)NSLAB * DIM];
static __device__ __align__(16) float g_pBv[(size_t)NSLAB * DIM];
static __device__ __align__(16) float g_pAw[(size_t)NSLAB * DIM];
static __device__ __align__(16) float g_pBw[(size_t)NSLAB * DIM];
static __device__ __align__(16) float g_Av[DIM];
static __device__ __align__(16) float g_Bv[DIM];
static __device__ __align__(16) float g_Aw[DIM];
static __device__ __align__(16) float g_Bw[DIM];
static __device__ __align__(16) float g_W[DIM + 4];   // W[i], i in [0,DIM]

// Monotonic ticket barrier state. NEVER reset -> safe across graph replays.
static __device__ unsigned long long g_bar = 0ULL;

// ---------------------------------------------------------------------------
// Grid-wide barrier. Tickets of barrier k occupy [k*GRID, (k+1)*GRID) because
// no block can reach barrier k+1 before barrier k releases. Deterministic,
// replay-safe (monotonic counter), graph-capturable (no API calls).
// REQUIRES all GRID blocks co-resident (launch_bounds(512,4): regs<=32 ->
// 4 blocks/SM -> 592 slots >= 512 blocks). Rounds 6-14 confirmed: no hang.
__device__ __forceinline__ void grid_barrier() {
    __syncthreads();
    if (threadIdx.x == 0) {
        __threadfence();                              // release prior writes
        const unsigned long long t = atomicAdd(&g_bar, 1ULL);
        const unsigned long long target = (t / GRID + 1ULL) * GRID;
        while (*((volatile unsigned long long*)&g_bar) < target)
            __nanosleep(64);
        __threadfence();                              // acquire others' writes
    }
    __syncthreads();
}

// ---------------------------------------------------------------------------
__global__ __launch_bounds__(NTHR, 4) void k_fused(
    const float* __restrict__ x,
    const float* __restrict__ v,
    const float* __restrict__ w,
    const float* __restrict__ y_p,
    const float* __restrict__ b_p,
    const float* __restrict__ u_p,
    const float* __restrict__ a_p,
    float* __restrict__ out)
{
    const int tid = threadIdx.x;
    const int bid = blockIdx.x;

    // ============ Phase 1: column statistics, one streaming pass over x ====
    // Block (xc, slab) covers 64 rows x 1024 cols; thread owns 2 columns.
    // Default cache policy on x (round-12: __ldcs here regresses).
    {
        const float u = u_p[0];
        const float a = a_p[0];
        const int xc = bid & (XCH - 1);
        const int slab = bid >> 2;
        const int col = xc * CCH + tid * 2;
        float av0 = 0.f, av1 = 0.f, bv0 = 0.f, bv1 = 0.f;
        float aw0 = 0.f, aw1 = 0.f, bw0 = 0.f, bw1 = 0.f;
        const float* xp = x + (size_t)slab * BROWS * DIM + col;
        const float* vp = v + slab * BROWS;
        const float* wp = w + slab * BROWS;
#pragma unroll 4
        for (int r = 0; r < BROWS; ++r) {
            const float vb = __ldg(&vp[r]);
            const float wb = __ldg(&wp[r]);
            const float2 xv = *(const float2*)(xp + (size_t)r * DIM);
            const float l0 = fmaf(u, xv.x, a);
            const float l1 = fmaf(u, xv.y, a);
            const float r0 = fmaxf(l0, 0.f);
            const float r1 = fmaxf(l1, 0.f);
            av0 = fmaf(vb, r0, av0);  aw0 = fmaf(wb, r0, aw0);
            av1 = fmaf(vb, r1, av1);  aw1 = fmaf(wb, r1, aw1);
            if (l0 > 0.f) { bv0 += vb; bw0 += wb; }
            if (l1 > 0.f) { bv1 += vb; bw1 += wb; }
        }
        const size_t po = (size_t)slab * DIM + col;
        *(float2*)&g_pAv[po] = make_float2(av0, av1);
        *(float2*)&g_pBv[po] = make_float2(bv0, bv1);
        *(float2*)&g_pAw[po] = make_float2(aw0, aw1);
        *(float2*)&g_pBw[po] = make_float2(bw0, bw1);
    }
    grid_barrier();

    // ============ Phase 2: reduce 128 slabs -> A/B vectors (8 cols/block) ==
    {
        __shared__ float sh[4][64][8];
        const int cl = tid & 7;          // column-local 0..7
        const int j  = tid >> 3;         // 0..63, sums 2 slabs each
        const int col = bid * 8 + cl;
        const size_t o0 = (size_t)(2 * j) * DIM + col;
        const size_t o1 = o0 + DIM;
        sh[0][j][cl] = g_pAv[o0] + g_pAv[o1];
        sh[1][j][cl] = g_pBv[o0] + g_pBv[o1];
        sh[2][j][cl] = g_pAw[o0] + g_pAw[o1];
        sh[3][j][cl] = g_pBw[o0] + g_pBw[o1];
        __syncthreads();
        if (tid < 32) {
            const int arr = tid >> 3;    // 0..3
            const int c = tid & 7;
            float s = 0.f;
#pragma unroll 8
            for (int k = 0; k < 64; ++k)
                s += sh[arr][k][c];
            const int gcol = bid * 8 + c;
            if      (arr == 0) g_Av[gcol] = s;
            else if (arr == 1) g_Bv[gcol] = s;
            else if (arr == 2) g_Aw[gcol] = s;
            else               g_Bw[gcol] = s;
        }
        __syncthreads();
    }
    grid_barrier();

    // ============ Phase 3: affine scan + W (block 0 only) ==================
    // V[i+1] = Av[i] + Bv[i]*V[i], V[0]=0; W[i+1] = Aw[i] + Bw[i]*V[i], W[0]=0
    if (bid == 0) {
        __shared__ float sa[NTHR];
        __shared__ float sb[NTHR];
        float la[8], lb[8];
        const int base = tid * 8;
        la[0] = g_Av[base];
        lb[0] = g_Bv[base];
#pragma unroll
        for (int k = 1; k < 8; ++k) {
            const float A = g_Av[base + k];
            const float B = g_Bv[base + k];
            la[k] = fmaf(B, la[k - 1], A);
            lb[k] = B * lb[k - 1];
        }
        sa[tid] = la[7];
        sb[tid] = lb[7];
        __syncthreads();
#pragma unroll
        for (int off = 1; off < NTHR; off <<= 1) {
            float pa = 0.f, pb = 0.f;
            const bool has = (tid >= off);
            if (has) { pa = sa[tid - off]; pb = sb[tid - off]; }
            __syncthreads();
            if (has) {
                sa[tid] = fmaf(sb[tid], pa, sa[tid]);
                sb[tid] = sb[tid] * pb;
            }
            __syncthreads();
        }
        const float pa = (tid > 0) ? sa[tid - 1] : 0.f;   // V[base]
        float V = pa;
#pragma unroll
        for (int k = 0; k < 8; ++k) {
            const int i = base + k;
            g_W[i + 1] = fmaf(g_Bw[i], V, g_Aw[i]);
            V = fmaf(lb[k], pa, la[k]);                   // V[i+1]
        }
        if (tid == 0) g_W[0] = 0.f;
    }
    grid_barrier();

    // ============ Phase 4: z + logdet (16 rows per block) ==================
    // g_W is written in phase 3 of THIS kernel -> COHERENT loads only
    // (__ldg here returned stale data: the round-6 failure).
    {
        __shared__ float smr[16];
        const float y0 = y_p[0];
        const float bb = b_p[0];
        const float ld_base = (float)DIM * logf(fabsf(y0));
        for (int rr = 0; rr < HID / GRID; ++rr) {
            const int row = rr * GRID + bid;
            const float4* __restrict__ xr = (const float4*)(x + (size_t)row * DIM);
            float4* __restrict__ zr = (float4*)(out + (size_t)row * DIM);
            float cnt = 0.f;
#pragma unroll
            for (int it = 0; it < DIM / 4 / NTHR; ++it) {   // 2 iterations
                const int c = it * NTHR + tid;
                const float4 xv = __ldcs(&xr[c]);
                const float4 wv = *(const float4*)&g_W[4 * c];   // coherent
                float4 z;
                const float l0 = fmaf(y0, xv.x, wv.x + bb);
                const float l1 = fmaf(y0, xv.y, wv.y + bb);
                const float l2 = fmaf(y0, xv.z, wv.z + bb);
                const float l3 = fmaf(y0, xv.w, wv.w + bb);
                z.x = (l0 >= 0.f) ? l0 : ALPHA * l0; if (l0 < 0.f) cnt += 1.f;
                z.y = (l1 >= 0.f) ? l1 : ALPHA * l1; if (l1 < 0.f) cnt += 1.f;
                z.z = (l2 >= 0.f) ? l2 : ALPHA * l2; if (l2 < 0.f) cnt += 1.f;
                z.w = (l3 >= 0.f) ? l3 : ALPHA * l3; if (l3 < 0.f) cnt += 1.f;
                __stcs(&zr[c], z);
            }
            // block reduce over 512 threads (16 warps)
#pragma unroll
            for (int o = 16; o > 0; o >>= 1)
                cnt += __shfl_xor_sync(0xffffffffu, cnt, o);
            if ((tid & 31) == 0) smr[tid >> 5] = cnt;
            __syncthreads();
            if (tid < 32) {
                float s = (tid < 16) ? smr[tid] : 0.f;
#pragma unroll
                for (int o = 8; o > 0; o >>= 1)
                    s += __shfl_xor_sync(0xffffffffu, s, o);
                if (tid == 0)
                    out[(size_t)HID * DIM + row] = s * LOG_ALPHA + ld_base;
            }
            __syncthreads();
        }
    }
}

// ---------------------------------------------------------------------------
extern "C" void kernel_launch(void* const* d_in, const int* in_sizes, int n_in,
                              void* d_out, int out_size)
{
    (void)in_sizes; (void)n_in; (void)out_size;
    const float* x = (const float*)d_in[0];   // [HID, DIM]
    const float* y = (const float*)d_in[1];   // [1]
    const float* w = (const float*)d_in[2];   // [HID]
    const float* b = (const float*)d_in[3];   // [1]
    const float* u = (const float*)d_in[4];   // [1]
    const float* v = (const float*)d_in[5];   // [HID]
    const float* a = (const float*)d_in[6];   // [1]
    float* out = (float*)d_out;               // [HID*DIM] z + [HID] logdet

    k_fused<<<GRID, NTHR>>>(x, v, w, y, b, u, a, out);
}

// round 16
// speedup vs baseline: 1.0560x; 1.0560x over previous
#include <cuda_runtime.h>
#include <math.h>

#define DIM 4096
#define HID 8192
#define ALPHA 0.1f
#define LOG_ALPHA -2.3025850929940457f

#define GRID  512
#define NTHR  512
#define NSLAB 128              // partial slabs
#define BROWS (HID / NSLAB)    // 64 rows per slab
#define XCH   4                // column chunks in phase 1
#define CCH   (DIM / XCH)      // 1024 cols per chunk

// Scratch (device globals). Partials: 4 x 2MB = 8MB.
static __device__ __align__(16) float g_pAv[(size_t)NSLAB * DIM];
static __device__ __align__(16) float g_pBv[(size_t)NSLAB * DIM];
static __device__ __align__(16) float g_pAw[(size_t)NSLAB * DIM];
static __device__ __align__(16) float g_pBw[(size_t)NSLAB * DIM];
static __device__ __align__(16) float g_Av[DIM];
static __device__ __align__(16) float g_Bv[DIM];
static __device__ __align__(16) float g_Aw[DIM];
static __device__ __align__(16) float g_Bw[DIM];
static __device__ __align__(16) float g_W[DIM + 4];   // W[i], i in [0,DIM]

// Monotonic ticket barrier state. NEVER reset -> safe across graph replays.
static __device__ unsigned long long g_bar = 0ULL;

// ---------------------------------------------------------------------------
// Grid-wide barrier (rounds 6-15 validated: deterministic, replay-safe,
// all 512 blocks co-resident under launch_bounds(512,4)).
__device__ __forceinline__ void grid_barrier() {
    __syncthreads();
    if (threadIdx.x == 0) {
        __threadfence();                              // release prior writes
        const unsigned long long t = atomicAdd(&g_bar, 1ULL);
        const unsigned long long target = (t / GRID + 1ULL) * GRID;
        while (*((volatile unsigned long long*)&g_bar) < target)
            __nanosleep(64);
        __threadfence();                              // acquire others' writes
    }
    __syncthreads();
}

// ---------------------------------------------------------------------------
// Kernel A: phases 1-3 fused (round-7 code, unchanged), produces g_W.
__global__ __launch_bounds__(NTHR, 4) void k_stats(
    const float* __restrict__ x,
    const float* __restrict__ v,
    const float* __restrict__ w,
    const float* __restrict__ u_p,
    const float* __restrict__ a_p)
{
    const int tid = threadIdx.x;
    const int bid = blockIdx.x;

    // ============ Phase 1: column statistics, one streaming pass over x ====
    {
        const float u = u_p[0];
        const float a = a_p[0];
        const int xc = bid & (XCH - 1);
        const int slab = bid >> 2;
        const int col = xc * CCH + tid * 2;
        float av0 = 0.f, av1 = 0.f, bv0 = 0.f, bv1 = 0.f;
        float aw0 = 0.f, aw1 = 0.f, bw0 = 0.f, bw1 = 0.f;
        const float* xp = x + (size_t)slab * BROWS * DIM + col;
        const float* vp = v + slab * BROWS;
        const float* wp = w + slab * BROWS;
#pragma unroll 4
        for (int r = 0; r < BROWS; ++r) {
            const float vb = __ldg(&vp[r]);
            const float wb = __ldg(&wp[r]);
            const float2 xv = *(const float2*)(xp + (size_t)r * DIM);
            const float l0 = fmaf(u, xv.x, a);
            const float l1 = fmaf(u, xv.y, a);
            const float r0 = fmaxf(l0, 0.f);
            const float r1 = fmaxf(l1, 0.f);
            av0 = fmaf(vb, r0, av0);  aw0 = fmaf(wb, r0, aw0);
            av1 = fmaf(vb, r1, av1);  aw1 = fmaf(wb, r1, aw1);
            if (l0 > 0.f) { bv0 += vb; bw0 += wb; }
            if (l1 > 0.f) { bv1 += vb; bw1 += wb; }
        }
        const size_t po = (size_t)slab * DIM + col;
        *(float2*)&g_pAv[po] = make_float2(av0, av1);
        *(float2*)&g_pBv[po] = make_float2(bv0, bv1);
        *(float2*)&g_pAw[po] = make_float2(aw0, aw1);
        *(float2*)&g_pBw[po] = make_float2(bw0, bw1);
    }
    grid_barrier();

    // ============ Phase 2: reduce 128 slabs -> A/B vectors (8 cols/block) ==
    {
        __shared__ float sh[4][64][8];
        const int cl = tid & 7;          // column-local 0..7
        const int j  = tid >> 3;         // 0..63, sums 2 slabs each
        const int col = bid * 8 + cl;
        const size_t o0 = (size_t)(2 * j) * DIM + col;
        const size_t o1 = o0 + DIM;
        sh[0][j][cl] = g_pAv[o0] + g_pAv[o1];
        sh[1][j][cl] = g_pBv[o0] + g_pBv[o1];
        sh[2][j][cl] = g_pAw[o0] + g_pAw[o1];
        sh[3][j][cl] = g_pBw[o0] + g_pBw[o1];
        __syncthreads();
        if (tid < 32) {
            const int arr = tid >> 3;    // 0..3
            const int c = tid & 7;
            float s = 0.f;
#pragma unroll 8
            for (int k = 0; k < 64; ++k)
                s += sh[arr][k][c];
            const int gcol = bid * 8 + c;
            if      (arr == 0) g_Av[gcol] = s;
            else if (arr == 1) g_Bv[gcol] = s;
            else if (arr == 2) g_Aw[gcol] = s;
            else               g_Bw[gcol] = s;
        }
        __syncthreads();
    }
    grid_barrier();

    // ============ Phase 3: affine scan + W (block 0 only) ==================
    // V[i+1] = Av[i] + Bv[i]*V[i], V[0]=0; W[i+1] = Aw[i] + Bw[i]*V[i], W[0]=0
    if (bid == 0) {
        __shared__ float sa[NTHR];
        __shared__ float sb[NTHR];
        float la[8], lb[8];
        const int base = tid * 8;
        la[0] = g_Av[base];
        lb[0] = g_Bv[base];
#pragma unroll
        for (int k = 1; k < 8; ++k) {
            const float A = g_Av[base + k];
            const float B = g_Bv[base + k];
            la[k] = fmaf(B, la[k - 1], A);
            lb[k] = B * lb[k - 1];
        }
        sa[tid] = la[7];
        sb[tid] = lb[7];
        __syncthreads();
#pragma unroll
        for (int off = 1; off < NTHR; off <<= 1) {
            float pa = 0.f, pb = 0.f;
            const bool has = (tid >= off);
            if (has) { pa = sa[tid - off]; pb = sb[tid - off]; }
            __syncthreads();
            if (has) {
                sa[tid] = fmaf(sb[tid], pa, sa[tid]);
                sb[tid] = sb[tid] * pb;
            }
            __syncthreads();
        }
        const float pa = (tid > 0) ? sa[tid - 1] : 0.f;   // V[base]
        float V = pa;
#pragma unroll
        for (int k = 0; k < 8; ++k) {
            const int i = base + k;
            g_W[i + 1] = fmaf(g_Bw[i], V, g_Aw[i]);
            V = fmaf(lb[k], pa, la[k]);                   // V[i+1]
        }
        if (tid == 0) g_W[0] = 0.f;
    }
}

// ---------------------------------------------------------------------------
// Kernel B: the round-5 standalone z kernel — free grid shape (8192 blocks),
// one block per row, reverse order. g_W written in a PREVIOUS launch, so
// __ldg is legal here (L1 flushed per launch; cross-launch coherence via L2).
__global__ __launch_bounds__(256) void k_z(
    const float* __restrict__ x,
    const float* __restrict__ y_p,
    const float* __restrict__ b_p,
    float* __restrict__ out)
{
    const int row = HID - 1 - blockIdx.x;             // reverse order
    const float y0 = y_p[0];
    const float bb = b_p[0];
    const float4* __restrict__ xr = (const float4*)(x + (size_t)row * DIM);
    float4* __restrict__ zr = (float4*)(out + (size_t)row * DIM);
    float cnt = 0.f;
#pragma unroll
    for (int j = 0; j < DIM / 4 / 256; ++j) {   // 4 iterations
        const int c = j * 256 + threadIdx.x;
        const float4 xv = __ldcs(&xr[c]);
        const float4 wv = __ldg((const float4*)&g_W[4 * c]);
        float4 z;
        const float l0 = fmaf(y0, xv.x, wv.x + bb);
        const float l1 = fmaf(y0, xv.y, wv.y + bb);
        const float l2 = fmaf(y0, xv.z, wv.z + bb);
        const float l3 = fmaf(y0, xv.w, wv.w + bb);
        z.x = (l0 >= 0.f) ? l0 : ALPHA * l0; if (l0 < 0.f) cnt += 1.f;
        z.y = (l1 >= 0.f) ? l1 : ALPHA * l1; if (l1 < 0.f) cnt += 1.f;
        z.z = (l2 >= 0.f) ? l2 : ALPHA * l2; if (l2 < 0.f) cnt += 1.f;
        z.w = (l3 >= 0.f) ? l3 : ALPHA * l3; if (l3 < 0.f) cnt += 1.f;
        __stcs(&zr[c], z);
    }
    // block reduce over 256 threads (8 warps)
    __shared__ float sm[8];
#pragma unroll
    for (int o = 16; o > 0; o >>= 1)
        cnt += __shfl_xor_sync(0xffffffffu, cnt, o);
    if ((threadIdx.x & 31) == 0) sm[threadIdx.x >> 5] = cnt;
    __syncthreads();
    if (threadIdx.x < 32) {
        float s = (threadIdx.x < 8) ? sm[threadIdx.x] : 0.f;
#pragma unroll
        for (int o = 4; o > 0; o >>= 1)
            s += __shfl_xor_sync(0xffffffffu, s, o);
        if (threadIdx.x == 0)
            out[(size_t)HID * DIM + row] =
                s * LOG_ALPHA + (float)DIM * logf(fabsf(y0));
    }
}

// ---------------------------------------------------------------------------
extern "C" void kernel_launch(void* const* d_in, const int* in_sizes, int n_in,
                              void* d_out, int out_size)
{
    (void)in_sizes; (void)n_in; (void)out_size;
    const float* x = (const float*)d_in[0];   // [HID, DIM]
    const float* y = (const float*)d_in[1];   // [1]
    const float* w = (const float*)d_in[2];   // [HID]
    const float* b = (const float*)d_in[3];   // [1]
    const float* u = (const float*)d_in[4];   // [1]
    const float* v = (const float*)d_in[5];   // [HID]
    const float* a = (const float*)d_in[6];   // [1]
    float* out = (float*)d_out;               // [HID*DIM] z + [HID] logdet

    k_stats<<<GRID, NTHR>>>(x, v, w, u, a);
    k_z<<<HID, 256>>>(x, y, b, out);
}

// round 17
// speedup vs baseline: 1.1201x; 1.0607x over previous
#include <cuda_runtime.h>
#include <math.h>

#define DIM 4096
#define HID 8192
#define ALPHA 0.1f
#define LOG_ALPHA -2.3025850929940457f

#define GRID  512              // k_stats grid (co-resident for barrier)
#define NTHR  256              // k_stats block
#define NSLAB 128              // partial slabs
#define BROWS (HID / NSLAB)    // 64 rows per slab
#define XCH   4                // column chunks in phase 1
#define ICH   (DIM / XCH)      // 1024 cols per chunk (256 thr x float4)

// Scratch (device globals). Partials: 4 x 2MB = 8MB.
static __device__ __align__(16) float g_pAv[(size_t)NSLAB * DIM];
static __device__ __align__(16) float g_pBv[(size_t)NSLAB * DIM];
static __device__ __align__(16) float g_pAw[(size_t)NSLAB * DIM];
static __device__ __align__(16) float g_pBw[(size_t)NSLAB * DIM];
static __device__ __align__(16) float g_Av[DIM];
static __device__ __align__(16) float g_Bv[DIM];
static __device__ __align__(16) float g_Aw[DIM];
static __device__ __align__(16) float g_Bw[DIM];
static __device__ __align__(16) float g_W[DIM + 4];   // W[i], i in [0,DIM]

// Monotonic ticket barrier state. NEVER reset -> safe across graph replays.
static __device__ unsigned long long g_bar = 0ULL;

// ---------------------------------------------------------------------------
// Grid-wide barrier (rounds 6-16 validated: deterministic, replay-safe).
// Co-residency: launch_bounds(256,4) caps regs at 64 -> >=4 blocks/SM ->
// 592 slots >= 512 blocks.
__device__ __forceinline__ void grid_barrier() {
    __syncthreads();
    if (threadIdx.x == 0) {
        __threadfence();                              // release prior writes
        const unsigned long long t = atomicAdd(&g_bar, 1ULL);
        const unsigned long long target = (t / GRID + 1ULL) * GRID;
        while (*((volatile unsigned long long*)&g_bar) < target)
            __nanosleep(64);
        __threadfence();                              // acquire others' writes
    }
    __syncthreads();
}

// ---------------------------------------------------------------------------
// Kernel A: phases 1-3. P1 uses the round-2/3 proven float4 reducer shape
// (512 blocks x 256 thr, 64-row slabs, 25.2us / 69.4% DRAM measured).
__global__ __launch_bounds__(NTHR, 4) void k_stats(
    const float* __restrict__ x,
    const float* __restrict__ v,
    const float* __restrict__ w,
    const float* __restrict__ u_p,
    const float* __restrict__ a_p)
{
    const int tid = threadIdx.x;
    const int bid = blockIdx.x;

    // ============ Phase 1: column statistics (float4 per thread) ===========
    {
        const float u = u_p[0];
        const float a = a_p[0];
        const int xc = bid & (XCH - 1);              // 0..3
        const int slab = bid >> 2;                   // 0..127
        const int col = xc * ICH + tid * 4;
        float4 Av = make_float4(0.f, 0.f, 0.f, 0.f);
        float4 Bv = make_float4(0.f, 0.f, 0.f, 0.f);
        float4 Aw = make_float4(0.f, 0.f, 0.f, 0.f);
        float4 Bw = make_float4(0.f, 0.f, 0.f, 0.f);
        const float* xp = x + (size_t)slab * BROWS * DIM + col;
        const float* vp = v + slab * BROWS;
        const float* wp = w + slab * BROWS;
#pragma unroll 4
        for (int r = 0; r < BROWS; ++r) {
            const float vb = __ldg(&vp[r]);
            const float wb = __ldg(&wp[r]);
            const float4 xv = *(const float4*)(xp + (size_t)r * DIM);
            const float l0 = fmaf(u, xv.x, a);
            const float l1 = fmaf(u, xv.y, a);
            const float l2 = fmaf(u, xv.z, a);
            const float l3 = fmaf(u, xv.w, a);
            const float r0 = fmaxf(l0, 0.f), r1 = fmaxf(l1, 0.f);
            const float r2 = fmaxf(l2, 0.f), r3 = fmaxf(l3, 0.f);
            Av.x = fmaf(vb, r0, Av.x);  Aw.x = fmaf(wb, r0, Aw.x);
            Av.y = fmaf(vb, r1, Av.y);  Aw.y = fmaf(wb, r1, Aw.y);
            Av.z = fmaf(vb, r2, Av.z);  Aw.z = fmaf(wb, r2, Aw.z);
            Av.w = fmaf(vb, r3, Av.w);  Aw.w = fmaf(wb, r3, Aw.w);
            if (l0 > 0.f) { Bv.x += vb; Bw.x += wb; }
            if (l1 > 0.f) { Bv.y += vb; Bw.y += wb; }
            if (l2 > 0.f) { Bv.z += vb; Bw.z += wb; }
            if (l3 > 0.f) { Bv.w += vb; Bw.w += wb; }
        }
        const size_t po = (size_t)slab * DIM + col;
        *(float4*)&g_pAv[po] = Av;
        *(float4*)&g_pBv[po] = Bv;
        *(float4*)&g_pAw[po] = Aw;
        *(float4*)&g_pBw[po] = Bw;
    }
    grid_barrier();

    // ============ Phase 2: reduce 128 slabs -> A/B vectors (8 cols/block) ==
    {
        __shared__ float shAv[32][8], shBv[32][8], shAw[32][8], shBw[32][8];
        const int cl = tid & 7;          // column-local 0..7
        const int j  = tid >> 3;         // 0..31, sums 4 slabs each
        const int col = bid * 8 + cl;
        float av = 0.f, bv = 0.f, aw = 0.f, bw = 0.f;
#pragma unroll
        for (int m = 0; m < 4; ++m) {
            const size_t o = (size_t)(j + 32 * m) * DIM + col;
            av += g_pAv[o]; bv += g_pBv[o];
            aw += g_pAw[o]; bw += g_pBw[o];
        }
        shAv[j][cl] = av; shBv[j][cl] = bv;
        shAw[j][cl] = aw; shBw[j][cl] = bw;
        __syncthreads();
        if (tid < 32) {
            const int arr = tid >> 3;    // 0..3
            const int c = tid & 7;
            const float (*p)[8] = (arr == 0) ? shAv :
                                  (arr == 1) ? shBv :
                                  (arr == 2) ? shAw : shBw;
            float s = 0.f;
#pragma unroll 8
            for (int k = 0; k < 32; ++k)
                s += p[k][c];
            const int gcol = bid * 8 + c;
            if      (arr == 0) g_Av[gcol] = s;
            else if (arr == 1) g_Bv[gcol] = s;
            else if (arr == 2) g_Aw[gcol] = s;
            else               g_Bw[gcol] = s;
        }
        __syncthreads();
    }
    grid_barrier();

    // ============ Phase 3: affine scan + W (block 0 only) ==================
    // V[i+1] = Av[i] + Bv[i]*V[i], V[0]=0; W[i+1] = Aw[i] + Bw[i]*V[i], W[0]=0
    // 256 threads x 16 elements each.
    if (bid == 0) {
        __shared__ float sa[NTHR];
        __shared__ float sb[NTHR];
        float la[16], lb[16];
        const int base = tid * 16;
        la[0] = g_Av[base];
        lb[0] = g_Bv[base];
#pragma unroll
        for (int k = 1; k < 16; ++k) {
            const float A = g_Av[base + k];
            const float B = g_Bv[base + k];
            la[k] = fmaf(B, la[k - 1], A);
            lb[k] = B * lb[k - 1];
        }
        sa[tid] = la[15];
        sb[tid] = lb[15];
        __syncthreads();
#pragma unroll
        for (int off = 1; off < NTHR; off <<= 1) {
            float pa = 0.f, pb = 0.f;
            const bool has = (tid >= off);
            if (has) { pa = sa[tid - off]; pb = sb[tid - off]; }
            __syncthreads();
            if (has) {
                sa[tid] = fmaf(sb[tid], pa, sa[tid]);
                sb[tid] = sb[tid] * pb;
            }
            __syncthreads();
        }
        const float pa = (tid > 0) ? sa[tid - 1] : 0.f;   // V[base]
        float V = pa;
#pragma unroll
        for (int k = 0; k < 16; ++k) {
            const int i = base + k;
            g_W[i + 1] = fmaf(g_Bw[i], V, g_Aw[i]);
            V = fmaf(lb[k], pa, la[k]);                   // V[i+1]
        }
        if (tid == 0) g_W[0] = 0.f;
    }
}

// ---------------------------------------------------------------------------
// Kernel B: standalone z kernel (round-16 verbatim) — free grid shape,
// one block per row, reverse order. g_W written in a PREVIOUS launch, so
// __ldg is legal here (L1 flushed per launch; cross-launch coherence via L2).
__global__ __launch_bounds__(256) void k_z(
    const float* __restrict__ x,
    const float* __restrict__ y_p,
    const float* __restrict__ b_p,
    float* __restrict__ out)
{
    const int row = HID - 1 - blockIdx.x;             // reverse order
    const float y0 = y_p[0];
    const float bb = b_p[0];
    const float4* __restrict__ xr = (const float4*)(x + (size_t)row * DIM);
    float4* __restrict__ zr = (float4*)(out + (size_t)row * DIM);
    float cnt = 0.f;
#pragma unroll
    for (int j = 0; j < DIM / 4 / 256; ++j) {   // 4 iterations
        const int c = j * 256 + threadIdx.x;
        const float4 xv = __ldcs(&xr[c]);
        const float4 wv = __ldg((const float4*)&g_W[4 * c]);
        float4 z;
        const float l0 = fmaf(y0, xv.x, wv.x + bb);
        const float l1 = fmaf(y0, xv.y, wv.y + bb);
        const float l2 = fmaf(y0, xv.z, wv.z + bb);
        const float l3 = fmaf(y0, xv.w, wv.w + bb);
        z.x = (l0 >= 0.f) ? l0 : ALPHA * l0; if (l0 < 0.f) cnt += 1.f;
        z.y = (l1 >= 0.f) ? l1 : ALPHA * l1; if (l1 < 0.f) cnt += 1.f;
        z.z = (l2 >= 0.f) ? l2 : ALPHA * l2; if (l2 < 0.f) cnt += 1.f;
        z.w = (l3 >= 0.f) ? l3 : ALPHA * l3; if (l3 < 0.f) cnt += 1.f;
        __stcs(&zr[c], z);
    }
    // block reduce over 256 threads (8 warps)
    __shared__ float sm[8];
#pragma unroll
    for (int o = 16; o > 0; o >>= 1)
        cnt += __shfl_xor_sync(0xffffffffu, cnt, o);
    if ((threadIdx.x & 31) == 0) sm[threadIdx.x >> 5] = cnt;
    __syncthreads();
    if (threadIdx.x < 32) {
        float s = (threadIdx.x < 8) ? sm[threadIdx.x] : 0.f;
#pragma unroll
        for (int o = 4; o > 0; o >>= 1)
            s += __shfl_xor_sync(0xffffffffu, s, o);
        if (threadIdx.x == 0)
            out[(size_t)HID * DIM + row] =
                s * LOG_ALPHA + (float)DIM * logf(fabsf(y0));
    }
}

// ---------------------------------------------------------------------------
extern "C" void kernel_launch(void* const* d_in, const int* in_sizes, int n_in,
                              void* d_out, int out_size)
{
    (void)in_sizes; (void)n_in; (void)out_size;
    const float* x = (const float*)d_in[0];   // [HID, DIM]
    const float* y = (const float*)d_in[1];   // [1]
    const float* w = (const float*)d_in[2];   // [HID]
    const float* b = (const float*)d_in[3];   // [1]
    const float* u = (const float*)d_in[4];   // [1]
    const float* v = (const float*)d_in[5];   // [HID]
    const float* a = (const float*)d_in[6];   // [1]
    float* out = (float*)d_out;               // [HID*DIM] z + [HID] logdet

    k_stats<<<GRID, NTHR>>>(x, v, w, u, a);
    k_z<<<HID, 256>>>(x, y, b, out);
}